// round 6
// baseline (speedup 1.0000x reference)
#include <cuda_runtime.h>
#include <math.h>

// Problem constants
#define NTOK 8192   // B*T
#define DDIM 1024   // D
#define LDIM 512    // L
#define VSZ  8192   // V

// ---------------- scratch (static __device__ — no runtime allocation) ----------------
__device__ float g_Pin  [NTOK * LDIM];   // x@W_in + b_in (pre-norm)
__device__ float g_A    [NTOK * LDIM];   // l2norm(P_in)
__device__ float g_Pcode[VSZ  * LDIM];   // codebook@W_code + b_code (pre-norm)
__device__ float g_C    [VSZ  * LDIM];   // l2norm(l2norm(P_code))
__device__ float g_b2   [VSZ];           // sum(C*C) per code row
__device__ unsigned long long g_best[NTOK];
__device__ int    g_idx  [NTOK];
__device__ int    g_count[VSZ];
__device__ double g_sum1;                // sum (q - x)^2 over N*D
__device__ double g_sum2;                // sum (Pcode[idx] - Pin)^2 over N*L

// ---------------- helpers ----------------
__device__ __forceinline__ unsigned int fkey(float f) {
    unsigned int u = __float_as_uint(f);
    return (u & 0x80000000u) ? ~u : (u | 0x80000000u);   // order-preserving map
}

// block sum over `nthreads` threads (128 or 256); all threads receive the result
__device__ __forceinline__ float blockSum(float v, int nthreads) {
    __shared__ float sh[8];
    int lane = threadIdx.x & 31, w = threadIdx.x >> 5, nw = nthreads >> 5;
    #pragma unroll
    for (int o = 16; o; o >>= 1) v += __shfl_down_sync(0xffffffffu, v, o);
    if (lane == 0) sh[w] = v;
    __syncthreads();
    float r = 0.f;
    if (threadIdx.x == 0) {
        for (int i = 0; i < nw; i++) r += sh[i];
        sh[0] = r;
    }
    __syncthreads();
    r = sh[0];
    __syncthreads();
    return r;
}

// ---------------- init ----------------
__global__ void k_init() {
    int i = blockIdx.x * blockDim.x + threadIdx.x;
    if (i < VSZ)  g_count[i] = 0;
    if (i < NTOK) g_best[i] = 0xFFFFFFFFFFFFFFFFull;
    if (i == 0) { g_sum1 = 0.0; g_sum2 = 0.0; }
}

// ---------------- fp32 GEMM  C[M,N] = A[M,K] @ B[K,N] + bias[N] ----------------
__global__ __launch_bounds__(256) void k_gemm_bias(
    const float* __restrict__ A, const float* __restrict__ B,
    const float* __restrict__ bias, float* __restrict__ C,
    int M, int N, int K)
{
    __shared__ float As[8][128];
    __shared__ float Bs[8][128];
    const int tid = threadIdx.x;
    const int bm0 = blockIdx.y * 128;
    const int bn0 = blockIdx.x * 128;
    const int tx = tid & 15, ty = tid >> 4;
    const int row = ty * 8, col = tx * 8;

    float acc[8][8];
    #pragma unroll
    for (int i = 0; i < 8; i++)
        #pragma unroll
        for (int j = 0; j < 8; j++) acc[i][j] = 0.f;

    const int aRow = tid >> 1;          // 0..127
    const int aCol = (tid & 1) * 4;     // 0 or 4
    const int bRow = tid >> 5;          // 0..7
    const int bCol = (tid & 31) * 4;    // 0..124

    const float* Ap = A + (size_t)(bm0 + aRow) * K + aCol;

    for (int k0 = 0; k0 < K; k0 += 8) {
        float4 av = *(const float4*)(Ap + k0);
        As[aCol + 0][aRow] = av.x;
        As[aCol + 1][aRow] = av.y;
        As[aCol + 2][aRow] = av.z;
        As[aCol + 3][aRow] = av.w;
        *(float4*)&Bs[bRow][bCol] =
            *(const float4*)&B[(size_t)(k0 + bRow) * N + bn0 + bCol];
        __syncthreads();
        #pragma unroll
        for (int k = 0; k < 8; k++) {
            float4 a0 = *(const float4*)&As[k][row];
            float4 a1 = *(const float4*)&As[k][row + 4];
            float4 b0 = *(const float4*)&Bs[k][col];
            float4 b1 = *(const float4*)&Bs[k][col + 4];
            float ar[8] = {a0.x, a0.y, a0.z, a0.w, a1.x, a1.y, a1.z, a1.w};
            float br[8] = {b0.x, b0.y, b0.z, b0.w, b1.x, b1.y, b1.z, b1.w};
            #pragma unroll
            for (int i = 0; i < 8; i++)
                #pragma unroll
                for (int j = 0; j < 8; j++)
                    acc[i][j] += ar[i] * br[j];
        }
        __syncthreads();
    }

    #pragma unroll
    for (int i = 0; i < 8; i++) {
        size_t r = (size_t)(bm0 + row + i) * N + bn0 + col;
        #pragma unroll
        for (int j = 0; j < 8; j++)
            C[r + j] = acc[i][j] + bias[bn0 + col + j];
    }
}

// ---------------- row L2 norms ----------------
__global__ void k_rownorm(const float* __restrict__ P, float* __restrict__ Out) {
    int rw = blockIdx.x, t = threadIdx.x;
    float4 v = ((const float4*)(P + (size_t)rw * LDIM))[t];
    float s = blockSum(v.x*v.x + v.y*v.y + v.z*v.z + v.w*v.w, 128);
    float r = rsqrtf(s + 1e-12f);
    ((float4*)(Out + (size_t)rw * LDIM))[t] = make_float4(v.x*r, v.y*r, v.z*r, v.w*r);
}

// codes: double normalization (matches reference), exact ||b||^2 on stored values
__global__ void k_codenorm(const float* __restrict__ P) {
    int rw = blockIdx.x, t = threadIdx.x;
    float4 v = ((const float4*)(P + (size_t)rw * LDIM))[t];
    float s1 = blockSum(v.x*v.x + v.y*v.y + v.z*v.z + v.w*v.w, 128);
    float r1 = rsqrtf(s1 + 1e-12f);
    v = make_float4(v.x*r1, v.y*r1, v.z*r1, v.w*r1);
    float s2 = blockSum(v.x*v.x + v.y*v.y + v.z*v.z + v.w*v.w, 128);
    float r2 = rsqrtf(s2 + 1e-12f);
    v = make_float4(v.x*r2, v.y*r2, v.z*r2, v.w*r2);
    float s3 = blockSum(v.x*v.x + v.y*v.y + v.z*v.z + v.w*v.w, 128);
    ((float4*)(g_C + (size_t)rw * LDIM))[t] = v;
    if (t == 0) g_b2[rw] = s3;
}

// ---------------- fused distance + argmin (NT GEMM, dominant 68.7 GF) ----------------
// score(n,v) = b2[v] - 2*dot(A[n,:], C[v,:]); ||a||^2 is row-constant -> dropped
__global__ __launch_bounds__(256) void k_argmin(
    const float* __restrict__ A, const float* __restrict__ Cc)
{
    __shared__ float As[8][128];
    __shared__ float Cs[8][128];
    __shared__ unsigned long long red[128 * 16];

    const int tid = threadIdx.x;
    const int bm0 = blockIdx.y * 128;   // token tile
    const int bv0 = blockIdx.x * 128;   // code tile
    const int tx = tid & 15, ty = tid >> 4;
    const int row = ty * 8, col = tx * 8;

    float acc[8][8];
    #pragma unroll
    for (int i = 0; i < 8; i++)
        #pragma unroll
        for (int j = 0; j < 8; j++) acc[i][j] = 0.f;

    const int aRow = tid >> 1;
    const int aCol = (tid & 1) * 4;
    const float* Ap = A  + (size_t)(bm0 + aRow) * LDIM + aCol;
    const float* Cp = Cc + (size_t)(bv0 + aRow) * LDIM + aCol;

    for (int k0 = 0; k0 < LDIM; k0 += 8) {
        float4 av = *(const float4*)(Ap + k0);
        As[aCol + 0][aRow] = av.x;
        As[aCol + 1][aRow] = av.y;
        As[aCol + 2][aRow] = av.z;
        As[aCol + 3][aRow] = av.w;
        float4 cv = *(const float4*)(Cp + k0);
        Cs[aCol + 0][aRow] = cv.x;
        Cs[aCol + 1][aRow] = cv.y;
        Cs[aCol + 2][aRow] = cv.z;
        Cs[aCol + 3][aRow] = cv.w;
        __syncthreads();
        #pragma unroll
        for (int k = 0; k < 8; k++) {
            float4 a0 = *(const float4*)&As[k][row];
            float4 a1 = *(const float4*)&As[k][row + 4];
            float4 b0 = *(const float4*)&Cs[k][col];
            float4 b1 = *(const float4*)&Cs[k][col + 4];
            float ar[8] = {a0.x, a0.y, a0.z, a0.w, a1.x, a1.y, a1.z, a1.w};
            float br[8] = {b0.x, b0.y, b0.z, b0.w, b1.x, b1.y, b1.z, b1.w};
            #pragma unroll
            for (int i = 0; i < 8; i++)
                #pragma unroll
                for (int j = 0; j < 8; j++)
                    acc[i][j] += ar[i] * br[j];
        }
        __syncthreads();
    }

    float b2r[8];
    #pragma unroll
    for (int j = 0; j < 8; j++) b2r[j] = g_b2[bv0 + col + j];

    #pragma unroll
    for (int i = 0; i < 8; i++) {
        unsigned long long m = 0xFFFFFFFFFFFFFFFFull;
        #pragma unroll
        for (int j = 0; j < 8; j++) {
            float s = b2r[j] - 2.f * acc[i][j];
            unsigned long long p =
                ((unsigned long long)fkey(s) << 32) | (unsigned int)(bv0 + col + j);
            if (p < m) m = p;
        }
        red[(row + i) * 16 + tx] = m;
    }
    __syncthreads();
    if (tid < 128) {
        unsigned long long m = red[tid * 16];
        #pragma unroll
        for (int t = 1; t < 16; t++) {
            unsigned long long p = red[tid * 16 + t];
            if (p < m) m = p;
        }
        atomicMin(&g_best[bm0 + tid], m);
    }
}

// ---------------- index extract + histogram ----------------
__global__ void k_hist() {
    int n = blockIdx.x * blockDim.x + threadIdx.x;
    if (n < NTOK) {
        int id = (int)(g_best[n] & 0xFFFFFFFFull);
        g_idx[n] = id;
        atomicAdd(&g_count[id], 1);
    }
}

// ---------------- quantized_st output + commit MSE ----------------
__global__ void k_quant(const float* __restrict__ x, const float* __restrict__ cb,
                        float* __restrict__ out)
{
    int n = blockIdx.x, t = threadIdx.x;
    int id = g_idx[n];
    float4 xv = ((const float4*)(x  + (size_t)n  * DDIM))[t];
    float4 qv = ((const float4*)(cb + (size_t)id * DDIM))[t];
    float4 d = make_float4(qv.x - xv.x, qv.y - xv.y, qv.z - xv.z, qv.w - xv.w);
    ((float4*)(out + (size_t)n * DDIM))[t] =
        make_float4(xv.x + d.x, xv.y + d.y, xv.z + d.z, xv.w + d.w);
    float loc = d.x*d.x + d.y*d.y + d.z*d.z + d.w*d.w;
    float s = blockSum(loc, 256);
    if (t == 0) atomicAdd(&g_sum1, (double)s);
}

// ---------------- latent-space MSE ----------------
__global__ void k_l2loss() {
    int n = blockIdx.x, t = threadIdx.x;
    int id = g_idx[n];
    float4 a = ((const float4*)(g_Pin   + (size_t)n  * LDIM))[t];
    float4 b = ((const float4*)(g_Pcode + (size_t)id * LDIM))[t];
    float4 d = make_float4(b.x - a.x, b.y - a.y, b.z - a.z, b.w - a.w);
    float loc = d.x*d.x + d.y*d.y + d.z*d.z + d.w*d.w;
    float s = blockSum(loc, 128);
    if (t == 0) atomicAdd(&g_sum2, (double)s);
}

// ---------------- final scalars: loss, perplexity, usage ----------------
__global__ void k_final(float* __restrict__ outScal) {
    __shared__ double shd[256];
    __shared__ int    shi[256];
    int t = threadIdx.x;
    double lp = 0.0;
    int used = 0;
    for (int v = t; v < VSZ; v += 256) {
        int c = g_count[v];
        if (c > 0) used++;
        float p = (float)c * (1.0f / 8192.0f);
        lp += (double)(-(p * logf(p + 1e-10f)));
    }
    shd[t] = lp; shi[t] = used;
    __syncthreads();
    for (int o = 128; o; o >>= 1) {
        if (t < o) { shd[t] += shd[t + o]; shi[t] += shi[t + o]; }
        __syncthreads();
    }
    if (t == 0) {
        float lpf = (float)shd[0];
        float m1 = (float)(g_sum1 / (double)((size_t)NTOK * DDIM));
        float m2 = (float)(g_sum2 / (double)((size_t)NTOK * LDIM));
        float loss = (0.25f * m1 + m1) + (0.25f * m2 + m2) + 0.1f * lpf;
        outScal[0] = loss;
        outScal[1] = expf(lpf);
        outScal[2] = (float)shi[0] / (float)VSZ;
    }
}

// ---------------- launch ----------------
extern "C" void kernel_launch(void* const* d_in, const int* in_sizes, int n_in,
                              void* d_out, int out_size)
{
    (void)in_sizes; (void)n_in;
    const float* x      = (const float*)d_in[0];
    const float* cb     = (const float*)d_in[1];
    const float* W_in   = (const float*)d_in[2];
    const float* b_in   = (const float*)d_in[3];
    const float* W_code = (const float*)d_in[4];
    const float* b_code = (const float*)d_in[5];
    float* out = (float*)d_out;

    // Resolve ALL device-symbol addresses host-side (passing a __device__
    // array directly as a kernel arg from host passes the host shadow
    // address — that was the R5 bug with g_C).
    void *pPin, *pA, *pPcode, *pC;
    cudaGetSymbolAddress(&pPin,   g_Pin);
    cudaGetSymbolAddress(&pA,     g_A);
    cudaGetSymbolAddress(&pPcode, g_Pcode);
    cudaGetSymbolAddress(&pC,     g_C);

    k_init<<<(VSZ + 255) / 256, 256>>>();

    // latent_input = l2norm(x @ W_in + b_in)
    k_gemm_bias<<<dim3(LDIM / 128, NTOK / 128), 256>>>(
        x, W_in, b_in, (float*)pPin, NTOK, LDIM, DDIM);
    k_rownorm<<<NTOK, 128>>>((const float*)pPin, (float*)pA);

    // latent_code (double-normalized) + exact ||b||^2
    k_gemm_bias<<<dim3(LDIM / 128, VSZ / 128), 256>>>(
        cb, W_code, b_code, (float*)pPcode, VSZ, LDIM, DDIM);
    k_codenorm<<<VSZ, 128>>>((const float*)pPcode);

    // fused distance + argmin (dominant cost)
    k_argmin<<<dim3(VSZ / 128, NTOK / 128), 256>>>(
        (const float*)pA, (const float*)pC);

    k_hist<<<(NTOK + 255) / 256, 256>>>();
    k_quant<<<NTOK, 256>>>(x, cb, out);
    k_l2loss<<<NTOK, 128>>>();
    k_final<<<1, 256>>>(out + (out_size - 3));
}

// round 7
// speedup vs baseline: 2.4637x; 2.4637x over previous
#include <cuda_runtime.h>
#include <cuda_bf16.h>
#include <cuda_fp16.h>
#include <math.h>

// Problem constants
#define NTOK 8192   // B*T
#define DDIM 1024   // D
#define LDIM 512    // L
#define VSZ  8192   // V

// Filter margin: >= 2*eps_mma(worst 7.8e-3 would need fully-correlated rounding;
// stochastic ~4e-4) + fp16 quant (~1e-3). Expected ~3 candidates/token.
#define DELTA 0.02f

// ---------------- scratch (static __device__ — no runtime allocation) ----------------
__device__ float g_Pin  [NTOK * LDIM];   // x@W_in + b_in (pre-norm)
__device__ float g_A    [NTOK * LDIM];   // l2norm(P_in)          (fp32, exact rescore)
__device__ float g_Pcode[VSZ  * LDIM];   // codebook@W_code + b_code (pre-norm)
__device__ float g_C    [VSZ  * LDIM];   // l2norm(l2norm(P_code)) (fp32, exact rescore)
__device__ __nv_bfloat16 g_Abf[NTOK * LDIM];  // bf16 copy for MMA
__device__ __nv_bfloat16 g_Cbf[VSZ  * LDIM];  // bf16 copy for MMA
__device__ __half g_S[(size_t)NTOK * VSZ];    // approx scores (fp16), 134MB
__device__ float g_b2   [VSZ];           // sum(C*C) per code row (exact)
__device__ unsigned long long g_best[NTOK];   // packed approx min (key<<32 | idx)
__device__ int    g_idx  [NTOK];
__device__ int    g_count[VSZ];
__device__ double g_sum1;                // sum (q - x)^2 over N*D
__device__ double g_sum2;                // sum (Pcode[idx] - Pin)^2 over N*L

// ---------------- helpers ----------------
__device__ __forceinline__ unsigned int fkey(float f) {
    unsigned int u = __float_as_uint(f);
    return (u & 0x80000000u) ? ~u : (u | 0x80000000u);   // order-preserving map
}
__device__ __forceinline__ float keyfloat(unsigned int k) {
    unsigned int u = (k & 0x80000000u) ? (k & 0x7FFFFFFFu) : ~k;
    return __uint_as_float(u);
}

// block sum; all threads receive the result
__device__ __forceinline__ float blockSum(float v, int nthreads) {
    __shared__ float sh[8];
    int lane = threadIdx.x & 31, w = threadIdx.x >> 5, nw = nthreads >> 5;
    #pragma unroll
    for (int o = 16; o; o >>= 1) v += __shfl_down_sync(0xffffffffu, v, o);
    if (lane == 0) sh[w] = v;
    __syncthreads();
    float r = 0.f;
    if (threadIdx.x == 0) {
        for (int i = 0; i < nw; i++) r += sh[i];
        sh[0] = r;
    }
    __syncthreads();
    r = sh[0];
    __syncthreads();
    return r;
}

__device__ __forceinline__ void mma16816(float* c, const unsigned int* a,
                                         unsigned int b0, unsigned int b1) {
    asm volatile(
        "mma.sync.aligned.m16n8k16.row.col.f32.bf16.bf16.f32 "
        "{%0,%1,%2,%3},{%4,%5,%6,%7},{%8,%9},{%0,%1,%2,%3};"
        : "+f"(c[0]), "+f"(c[1]), "+f"(c[2]), "+f"(c[3])
        : "r"(a[0]), "r"(a[1]), "r"(a[2]), "r"(a[3]), "r"(b0), "r"(b1));
}

// ---------------- init ----------------
__global__ void k_init() {
    int i = blockIdx.x * blockDim.x + threadIdx.x;
    if (i < VSZ)  g_count[i] = 0;
    if (i < NTOK) g_best[i] = 0xFFFFFFFFFFFFFFFFull;
    if (i == 0) { g_sum1 = 0.0; g_sum2 = 0.0; }
}

// ---------------- fp32 GEMM  C[M,N] = A[M,K] @ B[K,N] + bias[N] ----------------
// register-prefetch double buffer: LDG for chunk k+1 overlaps FFMA of chunk k
__global__ __launch_bounds__(256) void k_gemm_bias(
    const float* __restrict__ A, const float* __restrict__ B,
    const float* __restrict__ bias, float* __restrict__ C,
    int M, int N, int K)
{
    __shared__ float As[8][128];
    __shared__ float Bs[8][128];
    const int tid = threadIdx.x;
    const int bm0 = blockIdx.y * 128;
    const int bn0 = blockIdx.x * 128;
    const int tx = tid & 15, ty = tid >> 4;
    const int row = ty * 8, col = tx * 8;

    float acc[8][8];
    #pragma unroll
    for (int i = 0; i < 8; i++)
        #pragma unroll
        for (int j = 0; j < 8; j++) acc[i][j] = 0.f;

    const int aRow = tid >> 1;          // 0..127
    const int aCol = (tid & 1) * 4;     // 0 or 4
    const int bRow = tid >> 5;          // 0..7
    const int bCol = (tid & 31) * 4;    // 0..124

    const float* Ap = A + (size_t)(bm0 + aRow) * K + aCol;

    float4 av = *(const float4*)(Ap);
    float4 bv = *(const float4*)&B[(size_t)bRow * N + bn0 + bCol];

    for (int k0 = 0; k0 < K; k0 += 8) {
        As[aCol + 0][aRow] = av.x;
        As[aCol + 1][aRow] = av.y;
        As[aCol + 2][aRow] = av.z;
        As[aCol + 3][aRow] = av.w;
        *(float4*)&Bs[bRow][bCol] = bv;
        __syncthreads();
        if (k0 + 8 < K) {
            av = *(const float4*)(Ap + k0 + 8);
            bv = *(const float4*)&B[(size_t)(k0 + 8 + bRow) * N + bn0 + bCol];
        }
        #pragma unroll
        for (int k = 0; k < 8; k++) {
            float4 a0 = *(const float4*)&As[k][row];
            float4 a1 = *(const float4*)&As[k][row + 4];
            float4 b0 = *(const float4*)&Bs[k][col];
            float4 b1 = *(const float4*)&Bs[k][col + 4];
            float ar[8] = {a0.x, a0.y, a0.z, a0.w, a1.x, a1.y, a1.z, a1.w};
            float br[8] = {b0.x, b0.y, b0.z, b0.w, b1.x, b1.y, b1.z, b1.w};
            #pragma unroll
            for (int i = 0; i < 8; i++)
                #pragma unroll
                for (int j = 0; j < 8; j++)
                    acc[i][j] += ar[i] * br[j];
        }
        __syncthreads();
    }

    #pragma unroll
    for (int i = 0; i < 8; i++) {
        size_t r = (size_t)(bm0 + row + i) * N + bn0 + col;
        #pragma unroll
        for (int j = 0; j < 8; j++)
            C[r + j] = acc[i][j] + bias[bn0 + col + j];
    }
}

// ---------------- row L2 norm for tokens: g_Pin -> g_A (fp32) + g_Abf (bf16) ----------------
__global__ void k_rownorm() {
    int rw = blockIdx.x, t = threadIdx.x;
    float4 v = ((const float4*)(g_Pin + (size_t)rw * LDIM))[t];
    float s = blockSum(v.x*v.x + v.y*v.y + v.z*v.z + v.w*v.w, 128);
    float r = rsqrtf(s + 1e-12f);
    float4 o = make_float4(v.x*r, v.y*r, v.z*r, v.w*r);
    ((float4*)(g_A + (size_t)rw * LDIM))[t] = o;
    __nv_bfloat162* ob = (__nv_bfloat162*)(g_Abf + (size_t)rw * LDIM);
    ob[t * 2 + 0] = __floats2bfloat162_rn(o.x, o.y);
    ob[t * 2 + 1] = __floats2bfloat162_rn(o.z, o.w);
}

// codes: double normalization (matches reference), exact ||b||^2, fp32 + bf16 copies
__global__ void k_codenorm() {
    int rw = blockIdx.x, t = threadIdx.x;
    float4 v = ((const float4*)(g_Pcode + (size_t)rw * LDIM))[t];
    float s1 = blockSum(v.x*v.x + v.y*v.y + v.z*v.z + v.w*v.w, 128);
    float r1 = rsqrtf(s1 + 1e-12f);
    v = make_float4(v.x*r1, v.y*r1, v.z*r1, v.w*r1);
    float s2 = blockSum(v.x*v.x + v.y*v.y + v.z*v.z + v.w*v.w, 128);
    float r2 = rsqrtf(s2 + 1e-12f);
    v = make_float4(v.x*r2, v.y*r2, v.z*r2, v.w*r2);
    float s3 = blockSum(v.x*v.x + v.y*v.y + v.z*v.z + v.w*v.w, 128);
    ((float4*)(g_C + (size_t)rw * LDIM))[t] = v;
    __nv_bfloat162* ob = (__nv_bfloat162*)(g_Cbf + (size_t)rw * LDIM);
    ob[t * 2 + 0] = __floats2bfloat162_rn(v.x, v.y);
    ob[t * 2 + 1] = __floats2bfloat162_rn(v.z, v.w);
    if (t == 0) g_b2[rw] = s3;
}

// ---------------- bf16 tensor-core scorer ----------------
// Tile 128 tokens x 128 codes, K=512 in 8 chunks of 64. 8 warps: 4(m) x 2(n),
// warp tile 32x64 via mma.m16n8k16 (2 m-tiles x 8 n-tiles).
// Smem: 8x8 uint4-block XOR swizzle -> conflict-free LDS.32 fragment loads.
// Epilogue: s = b2[v] - 2*dot; store fp16 score matrix + per-row approx-min atomicMin.
__global__ __launch_bounds__(256) void k_score() {
    __shared__ __align__(16) __nv_bfloat16 As[128 * 64];
    __shared__ __align__(16) __nv_bfloat16 Cs[128 * 64];
    __shared__ unsigned long long red[128 * 2];

    const int tid = threadIdx.x;
    const int wid = tid >> 5, lane = tid & 31;
    const int warp_m = wid >> 1, warp_n = wid & 1;
    const int g = lane >> 2, q = lane & 3;
    const int bm0 = blockIdx.y * 128;   // token tile
    const int bv0 = blockIdx.x * 128;   // code tile

    float acc[2][8][4];
    #pragma unroll
    for (int mt = 0; mt < 2; mt++)
        #pragma unroll
        for (int nt = 0; nt < 8; nt++)
            #pragma unroll
            for (int i = 0; i < 4; i++) acc[mt][nt][i] = 0.f;

    const uint4* Ag = (const uint4*)(g_Abf + (size_t)bm0 * LDIM);
    const uint4* Cg = (const uint4*)(g_Cbf + (size_t)bv0 * LDIM);
    uint4* As4 = (uint4*)As;
    uint4* Cs4 = (uint4*)Cs;
    const unsigned int* As32 = (const unsigned int*)As;
    const unsigned int* Cs32 = (const unsigned int*)Cs;

    for (int kc = 0; kc < 8; kc++) {
        __syncthreads();   // previous chunk's compute done before overwrite
        #pragma unroll
        for (int i = 0; i < 4; i++) {
            int idx = tid + i * 256;            // 0..1023
            int row = idx >> 3, wq = idx & 7;   // 8 uint4 per 64-elem row
            As4[row * 8 + (wq ^ (row & 7))] = Ag[(size_t)row * 64 + kc * 8 + wq];
            Cs4[row * 8 + (wq ^ (row & 7))] = Cg[(size_t)row * 64 + kc * 8 + wq];
        }
        __syncthreads();
        #pragma unroll
        for (int ks = 0; ks < 4; ks++) {
            unsigned int af[2][4];
            #pragma unroll
            for (int mt = 0; mt < 2; mt++) {
                int r0 = warp_m * 32 + mt * 16 + g;
                int r1 = r0 + 8;
                af[mt][0] = As32[r0*32 + (((ks*2 + 0) ^ (r0 & 7)) << 2) + q];
                af[mt][1] = As32[r1*32 + (((ks*2 + 0) ^ (r1 & 7)) << 2) + q];
                af[mt][2] = As32[r0*32 + (((ks*2 + 1) ^ (r0 & 7)) << 2) + q];
                af[mt][3] = As32[r1*32 + (((ks*2 + 1) ^ (r1 & 7)) << 2) + q];
            }
            #pragma unroll
            for (int nt = 0; nt < 8; nt++) {
                int rc = warp_n * 64 + nt * 8 + g;
                unsigned int b0 = Cs32[rc*32 + (((ks*2 + 0) ^ (rc & 7)) << 2) + q];
                unsigned int b1 = Cs32[rc*32 + (((ks*2 + 1) ^ (rc & 7)) << 2) + q];
                mma16816(acc[0][nt], af[0], b0, b1);
                mma16816(acc[1][nt], af[1], b0, b1);
            }
        }
    }

    // epilogue: scores, fp16 store, per-row approx min
    unsigned long long km[2][2];
    km[0][0] = km[0][1] = km[1][0] = km[1][1] = 0xFFFFFFFFFFFFFFFFull;

    #pragma unroll
    for (int nt = 0; nt < 8; nt++) {
        int colG = bv0 + warp_n * 64 + nt * 8 + q * 2;
        float2 bb = *(const float2*)&g_b2[colG];
        #pragma unroll
        for (int mt = 0; mt < 2; mt++) {
            float s0 = bb.x - 2.f * acc[mt][nt][0];
            float s1 = bb.y - 2.f * acc[mt][nt][1];
            float s2 = bb.x - 2.f * acc[mt][nt][2];
            float s3 = bb.y - 2.f * acc[mt][nt][3];
            int r0 = bm0 + warp_m * 32 + mt * 16 + g;
            *(__half2*)&g_S[(size_t)r0 * VSZ + colG]       = __floats2half2_rn(s0, s1);
            *(__half2*)&g_S[(size_t)(r0 + 8) * VSZ + colG] = __floats2half2_rn(s2, s3);
            unsigned long long p0 =
                ((unsigned long long)fkey(s0) << 32) | (unsigned int)colG;
            unsigned long long p1 =
                ((unsigned long long)fkey(s1) << 32) | (unsigned int)(colG + 1);
            if (p1 < p0) p0 = p1;
            if (p0 < km[mt][0]) km[mt][0] = p0;
            unsigned long long p2 =
                ((unsigned long long)fkey(s2) << 32) | (unsigned int)colG;
            unsigned long long p3 =
                ((unsigned long long)fkey(s3) << 32) | (unsigned int)(colG + 1);
            if (p3 < p2) p2 = p3;
            if (p2 < km[mt][1]) km[mt][1] = p2;
        }
    }
    // reduce across the 4 lanes of each quad (same row)
    #pragma unroll
    for (int mt = 0; mt < 2; mt++)
        #pragma unroll
        for (int h = 0; h < 2; h++) {
            unsigned long long v = km[mt][h];
            #pragma unroll
            for (int off = 1; off < 4; off <<= 1) {
                unsigned long long o = __shfl_xor_sync(0xffffffffu, v, off);
                if (o < v) v = o;
            }
            km[mt][h] = v;
        }
    if (q == 0) {
        #pragma unroll
        for (int mt = 0; mt < 2; mt++)
            #pragma unroll
            for (int h = 0; h < 2; h++) {
                int r = warp_m * 32 + mt * 16 + h * 8 + g;
                red[r * 2 + warp_n] = km[mt][h];
            }
    }
    __syncthreads();
    if (tid < 128) {
        unsigned long long m = red[tid * 2];
        if (red[tid * 2 + 1] < m) m = red[tid * 2 + 1];
        atomicMin(&g_best[bm0 + tid], m);
    }
}

// ---------------- candidate filter + exact fp32 rescore (one block per token) ----------------
__global__ __launch_bounds__(256) void k_select() {
    const int n = blockIdx.x, tid = threadIdx.x;
    __shared__ int cnt;
    __shared__ int cand[256];
    __shared__ unsigned long long bestSh;
    if (tid == 0) { cnt = 0; bestSh = 0xFFFFFFFFFFFFFFFFull; }
    __syncthreads();

    const float thr = keyfloat((unsigned int)(g_best[n] >> 32)) + DELTA;
    const __half2* rowS = (const __half2*)(g_S + (size_t)n * VSZ);
    for (int v2 = tid; v2 < VSZ / 2; v2 += 256) {
        float2 f = __half22float2(rowS[v2]);
        if (f.x <= thr) { int p = atomicAdd(&cnt, 1); if (p < 256) cand[p] = v2 * 2; }
        if (f.y <= thr) { int p = atomicAdd(&cnt, 1); if (p < 256) cand[p] = v2 * 2 + 1; }
    }
    __syncthreads();
    int c = cnt;

    unsigned long long best = 0xFFFFFFFFFFFFFFFFull;
    if (c <= 256) {
        const float* ar = g_A + (size_t)n * LDIM;
        for (int i = 0; i < c; i++) {
            int v = cand[i];
            const float* cr = g_C + (size_t)v * LDIM;
            float part = ar[tid * 2] * cr[tid * 2] + ar[tid * 2 + 1] * cr[tid * 2 + 1];
            float s = blockSum(part, 256);
            float score = g_b2[v] - 2.f * s;
            unsigned long long p =
                ((unsigned long long)fkey(score) << 32) | (unsigned int)v;
            if (p < best) best = p;
        }
    } else {
        // safety fallback (statistically never): full exact scan for this token
        const float* ar = g_A + (size_t)n * LDIM;
        unsigned long long loc = 0xFFFFFFFFFFFFFFFFull;
        for (int v = tid; v < VSZ; v += 256) {
            const float* cr = g_C + (size_t)v * LDIM;
            float s = 0.f;
            for (int d = 0; d < LDIM; d++) s += ar[d] * cr[d];
            float score = g_b2[v] - 2.f * s;
            unsigned long long p =
                ((unsigned long long)fkey(score) << 32) | (unsigned int)v;
            if (p < loc) loc = p;
        }
        atomicMin(&bestSh, loc);
        __syncthreads();
        best = bestSh;
    }

    if (tid == 0) {
        int id = (int)(best & 0xFFFFFFFFull);
        g_idx[n] = id;
        atomicAdd(&g_count[id], 1);
    }
}

// ---------------- quantized_st output + commit MSE ----------------
__global__ void k_quant(const float* __restrict__ x, const float* __restrict__ cb,
                        float* __restrict__ out)
{
    int n = blockIdx.x, t = threadIdx.x;
    int id = g_idx[n];
    float4 xv = ((const float4*)(x  + (size_t)n  * DDIM))[t];
    float4 qv = ((const float4*)(cb + (size_t)id * DDIM))[t];
    float4 d = make_float4(qv.x - xv.x, qv.y - xv.y, qv.z - xv.z, qv.w - xv.w);
    ((float4*)(out + (size_t)n * DDIM))[t] =
        make_float4(xv.x + d.x, xv.y + d.y, xv.z + d.z, xv.w + d.w);
    float loc = d.x*d.x + d.y*d.y + d.z*d.z + d.w*d.w;
    float s = blockSum(loc, 256);
    if (t == 0) atomicAdd(&g_sum1, (double)s);
}

// ---------------- latent-space MSE ----------------
__global__ void k_l2loss() {
    int n = blockIdx.x, t = threadIdx.x;
    int id = g_idx[n];
    float4 a = ((const float4*)(g_Pin   + (size_t)n  * LDIM))[t];
    float4 b = ((const float4*)(g_Pcode + (size_t)id * LDIM))[t];
    float4 d = make_float4(b.x - a.x, b.y - a.y, b.z - a.z, b.w - a.w);
    float loc = d.x*d.x + d.y*d.y + d.z*d.z + d.w*d.w;
    float s = blockSum(loc, 128);
    if (t == 0) atomicAdd(&g_sum2, (double)s);
}

// ---------------- final scalars: loss, perplexity, usage ----------------
__global__ void k_final(float* __restrict__ outScal) {
    __shared__ double shd[256];
    __shared__ int    shi[256];
    int t = threadIdx.x;
    double lp = 0.0;
    int used = 0;
    for (int v = t; v < VSZ; v += 256) {
        int c = g_count[v];
        if (c > 0) used++;
        float p = (float)c * (1.0f / 8192.0f);
        lp += (double)(-(p * logf(p + 1e-10f)));
    }
    shd[t] = lp; shi[t] = used;
    __syncthreads();
    for (int o = 128; o; o >>= 1) {
        if (t < o) { shd[t] += shd[t + o]; shi[t] += shi[t + o]; }
        __syncthreads();
    }
    if (t == 0) {
        float lpf = (float)shd[0];
        float m1 = (float)(g_sum1 / (double)((size_t)NTOK * DDIM));
        float m2 = (float)(g_sum2 / (double)((size_t)NTOK * LDIM));
        float loss = (0.25f * m1 + m1) + (0.25f * m2 + m2) + 0.1f * lpf;
        outScal[0] = loss;
        outScal[1] = expf(lpf);
        outScal[2] = (float)shi[0] / (float)VSZ;
    }
}

// ---------------- launch ----------------
extern "C" void kernel_launch(void* const* d_in, const int* in_sizes, int n_in,
                              void* d_out, int out_size)
{
    (void)in_sizes; (void)n_in;
    const float* x      = (const float*)d_in[0];
    const float* cb     = (const float*)d_in[1];
    const float* W_in   = (const float*)d_in[2];
    const float* b_in   = (const float*)d_in[3];
    const float* W_code = (const float*)d_in[4];
    const float* b_code = (const float*)d_in[5];
    float* out = (float*)d_out;

    // Host-resolved device-symbol addresses for kernels that take them as args.
    // (All other kernels reference __device__ globals directly from device code.)
    void *pPin, *pPcode;
    cudaGetSymbolAddress(&pPin,   g_Pin);
    cudaGetSymbolAddress(&pPcode, g_Pcode);

    k_init<<<(VSZ + 255) / 256, 256>>>();

    // latent_input = l2norm(x @ W_in + b_in); fp32 + bf16 copies
    k_gemm_bias<<<dim3(LDIM / 128, NTOK / 128), 256>>>(
        x, W_in, b_in, (float*)pPin, NTOK, LDIM, DDIM);
    k_rownorm<<<NTOK, 128>>>();

    // latent_code (double-normalized) + exact ||b||^2; fp32 + bf16 copies
    k_gemm_bias<<<dim3(LDIM / 128, VSZ / 128), 256>>>(
        cb, W_code, b_code, (float*)pPcode, VSZ, LDIM, DDIM);
    k_codenorm<<<VSZ, 128>>>();

    // bf16 tensor-core scoring: fp16 score matrix + approx per-token min
    k_score<<<dim3(VSZ / 128, NTOK / 128), 256>>>();

    // epsilon-filter + exact fp32 rescore -> final indices + histogram
    k_select<<<NTOK, 256>>>();

    k_quant<<<NTOK, 256>>>(x, cb, out);
    k_l2loss<<<NTOK, 128>>>();
    k_final<<<1, 256>>>(out + (out_size - 3));
}

// round 8
// speedup vs baseline: 2.7497x; 1.1161x over previous
#include <cuda_runtime.h>
#include <cuda_bf16.h>
#include <cuda_fp16.h>
#include <math.h>

// Problem constants
#define NTOK 8192   // B*T
#define DDIM 1024   // D
#define LDIM 512    // L
#define VSZ  8192   // V

// Filter margin for the bf16 scorer (see R7 analysis)
#define DELTA 0.02f

// smem row pad (floats) for the tf32 GEMM: bank = (4*row + q) % 32 -> conflict-free
#define PAD 20

// ---------------- scratch (static __device__ — no runtime allocation) ----------------
__device__ float g_Pin  [NTOK * LDIM];   // x@W_in + b_in (pre-norm)
__device__ float g_A    [NTOK * LDIM];   // l2norm(P_in)          (fp32, exact rescore)
__device__ float g_Pcode[VSZ  * LDIM];   // codebook@W_code + b_code (pre-norm)
__device__ float g_C    [VSZ  * LDIM];   // l2norm(l2norm(P_code)) (fp32, exact rescore)
__device__ __nv_bfloat16 g_Abf[NTOK * LDIM];  // bf16 copy for MMA scorer
__device__ __nv_bfloat16 g_Cbf[VSZ  * LDIM];  // bf16 copy for MMA scorer
__device__ __half g_S[(size_t)NTOK * VSZ];    // approx scores (fp16), 134MB
__device__ float g_b2   [VSZ];           // sum(C*C) per code row (exact)
__device__ unsigned long long g_best[NTOK];   // packed approx min (key<<32 | idx)
__device__ int    g_idx  [NTOK];
__device__ int    g_count[VSZ];
__device__ double g_sum1;                // sum (q - x)^2 over N*D
__device__ double g_sum2;                // sum (Pcode[idx] - Pin)^2 over N*L

// ---------------- helpers ----------------
__device__ __forceinline__ unsigned int fkey(float f) {
    unsigned int u = __float_as_uint(f);
    return (u & 0x80000000u) ? ~u : (u | 0x80000000u);   // order-preserving map
}
__device__ __forceinline__ float keyfloat(unsigned int k) {
    unsigned int u = (k & 0x80000000u) ? (k & 0x7FFFFFFFu) : ~k;
    return __uint_as_float(u);
}

// block sum; all threads receive the result
__device__ __forceinline__ float blockSum(float v, int nthreads) {
    __shared__ float sh[8];
    int lane = threadIdx.x & 31, w = threadIdx.x >> 5, nw = nthreads >> 5;
    #pragma unroll
    for (int o = 16; o; o >>= 1) v += __shfl_down_sync(0xffffffffu, v, o);
    if (lane == 0) sh[w] = v;
    __syncthreads();
    float r = 0.f;
    if (threadIdx.x == 0) {
        for (int i = 0; i < nw; i++) r += sh[i];
        sh[0] = r;
    }
    __syncthreads();
    r = sh[0];
    __syncthreads();
    return r;
}

__device__ __forceinline__ void mma16816(float* c, const unsigned int* a,
                                         unsigned int b0, unsigned int b1) {
    asm volatile(
        "mma.sync.aligned.m16n8k16.row.col.f32.bf16.bf16.f32 "
        "{%0,%1,%2,%3},{%4,%5,%6,%7},{%8,%9},{%0,%1,%2,%3};"
        : "+f"(c[0]), "+f"(c[1]), "+f"(c[2]), "+f"(c[3])
        : "r"(a[0]), "r"(a[1]), "r"(a[2]), "r"(a[3]), "r"(b0), "r"(b1));
}

__device__ __forceinline__ void mma_tf32(float* c, const unsigned int* a,
                                         unsigned int b0, unsigned int b1) {
    asm volatile(
        "mma.sync.aligned.m16n8k8.row.col.f32.tf32.tf32.f32 "
        "{%0,%1,%2,%3},{%4,%5,%6,%7},{%8,%9},{%0,%1,%2,%3};"
        : "+f"(c[0]), "+f"(c[1]), "+f"(c[2]), "+f"(c[3])
        : "r"(a[0]), "r"(a[1]), "r"(a[2]), "r"(a[3]), "r"(b0), "r"(b1));
}

__device__ __forceinline__ float tf32r(float x) {
    float r; asm("cvt.rna.tf32.f32 %0, %1;" : "=f"(r) : "f"(x)); return r;
}

// ---------------- init ----------------
__global__ void k_init() {
    int i = blockIdx.x * blockDim.x + threadIdx.x;
    if (i < VSZ)  g_count[i] = 0;
    if (i < NTOK) g_best[i] = 0xFFFFFFFFFFFFFFFFull;
    if (i == 0) { g_sum1 = 0.0; g_sum2 = 0.0; }
}

// ---------------- tf32 3-pass GEMM: C[M,N] = A[M,K] @ B[K,N] + bias[N] ----------------
// fp32-faithful via hi/lo split: D = Ah*Bh + Ah*Bl + Al*Bh (fp32 accumulate).
// Tile 128x128, BK=16, 8 warps (4m x 2n), warp tile 32x64 via m16n8k8.
// Smem rows padded to PAD=20 floats -> conflict-free fragment LDS.
__global__ __launch_bounds__(256) void k_gemm_tf32(
    const float* __restrict__ A, const float* __restrict__ B,
    const float* __restrict__ bias, float* __restrict__ C,
    int M, int N, int K)
{
    __shared__ __align__(16) float Ah[128 * PAD], Al[128 * PAD];
    __shared__ __align__(16) float Bh[128 * PAD], Bl[128 * PAD];

    const int tid = threadIdx.x;
    const int lane = tid & 31;
    const int wid = tid >> 5;
    const int warp_m = wid >> 1, warp_n = wid & 1;
    const int g = lane >> 2, q = lane & 3;
    const int bm0 = blockIdx.y * 128, bn0 = blockIdx.x * 128;

    float acc[2][8][4];
    #pragma unroll
    for (int mt = 0; mt < 2; mt++)
        #pragma unroll
        for (int nt = 0; nt < 8; nt++)
            #pragma unroll
            for (int i = 0; i < 4; i++) acc[mt][nt][i] = 0.f;

    // A loader: each thread owns row = tid>>1, 8 consecutive k at (tid&1)*8
    const int arow = tid >> 1, ahalf = (tid & 1) * 8;
    const float* Ap = A + (size_t)(bm0 + arow) * K + ahalf;
    // B loader: each thread owns column n = tid&127, two k-groups {kg, kg+2} (kg = tid>>7)
    const int bn = tid & 127, bkg = tid >> 7;        // bkg in {0,1}
    const float* Bp = B + bn0 + bn;

    // prefetch chunk 0
    float4 av0 = *(const float4*)(Ap);
    float4 av1 = *(const float4*)(Ap + 4);
    float bv[2][4];
    #pragma unroll
    for (int t = 0; t < 2; t++) {
        int kb = (bkg + 2 * t) * 4;
        #pragma unroll
        for (int kk = 0; kk < 4; kk++)
            bv[t][kk] = Bp[(size_t)(kb + kk) * N];
    }

    const unsigned int* Ah32 = (const unsigned int*)Ah;
    const unsigned int* Al32 = (const unsigned int*)Al;
    const unsigned int* Bh32 = (const unsigned int*)Bh;
    const unsigned int* Bl32 = (const unsigned int*)Bl;

    const int nchunks = K / 16;
    for (int kc = 0; kc < nchunks; kc++) {
        // hi/lo split + smem store (STS.128)
        {
            float va[8] = {av0.x, av0.y, av0.z, av0.w, av1.x, av1.y, av1.z, av1.w};
            float h[8], l[8];
            #pragma unroll
            for (int i = 0; i < 8; i++) {
                h[i] = tf32r(va[i]);
                l[i] = tf32r(va[i] - h[i]);
            }
            int base = arow * PAD + ahalf;
            *(float4*)&Ah[base]     = make_float4(h[0], h[1], h[2], h[3]);
            *(float4*)&Ah[base + 4] = make_float4(h[4], h[5], h[6], h[7]);
            *(float4*)&Al[base]     = make_float4(l[0], l[1], l[2], l[3]);
            *(float4*)&Al[base + 4] = make_float4(l[4], l[5], l[6], l[7]);
        }
        #pragma unroll
        for (int t = 0; t < 2; t++) {
            int kb = (bkg + 2 * t) * 4;
            float h[4], l[4];
            #pragma unroll
            for (int kk = 0; kk < 4; kk++) {
                h[kk] = tf32r(bv[t][kk]);
                l[kk] = tf32r(bv[t][kk] - h[kk]);
            }
            int base = bn * PAD + kb;
            *(float4*)&Bh[base] = make_float4(h[0], h[1], h[2], h[3]);
            *(float4*)&Bl[base] = make_float4(l[0], l[1], l[2], l[3]);
        }
        __syncthreads();

        // prefetch next chunk
        if (kc + 1 < nchunks) {
            int ko = (kc + 1) * 16;
            av0 = *(const float4*)(Ap + ko);
            av1 = *(const float4*)(Ap + ko + 4);
            #pragma unroll
            for (int t = 0; t < 2; t++) {
                int kb = ko + (bkg + 2 * t) * 4;
                #pragma unroll
                for (int kk = 0; kk < 4; kk++)
                    bv[t][kk] = Bp[(size_t)(kb + kk) * N];
            }
        }

        // compute: 2 k-steps of 8
        #pragma unroll
        for (int ks = 0; ks < 2; ks++) {
            unsigned int ah[2][4], al[2][4];
            #pragma unroll
            for (int mt = 0; mt < 2; mt++) {
                int r = warp_m * 32 + mt * 16 + g;
                int i0 = r * PAD + ks * 8 + q;
                ah[mt][0] = Ah32[i0];
                ah[mt][1] = Ah32[i0 + 8 * PAD];
                ah[mt][2] = Ah32[i0 + 4];
                ah[mt][3] = Ah32[i0 + 8 * PAD + 4];
                al[mt][0] = Al32[i0];
                al[mt][1] = Al32[i0 + 8 * PAD];
                al[mt][2] = Al32[i0 + 4];
                al[mt][3] = Al32[i0 + 8 * PAD + 4];
            }
            #pragma unroll
            for (int nt = 0; nt < 8; nt++) {
                int rc = warp_n * 64 + nt * 8 + g;
                int bi = rc * PAD + ks * 8 + q;
                unsigned int bh0 = Bh32[bi], bh1 = Bh32[bi + 4];
                unsigned int bl0 = Bl32[bi], bl1 = Bl32[bi + 4];
                #pragma unroll
                for (int mt = 0; mt < 2; mt++) {
                    mma_tf32(acc[mt][nt], ah[mt], bh0, bh1);
                    mma_tf32(acc[mt][nt], ah[mt], bl0, bl1);
                    mma_tf32(acc[mt][nt], al[mt], bh0, bh1);
                }
            }
        }
        __syncthreads();
    }

    // epilogue: + bias, float2 stores
    #pragma unroll
    for (int mt = 0; mt < 2; mt++) {
        int row = bm0 + warp_m * 32 + mt * 16 + g;
        #pragma unroll
        for (int nt = 0; nt < 8; nt++) {
            int col = bn0 + warp_n * 64 + nt * 8 + 2 * q;
            float2 bb = *(const float2*)&bias[col];
            float2 c0 = make_float2(acc[mt][nt][0] + bb.x, acc[mt][nt][1] + bb.y);
            float2 c1 = make_float2(acc[mt][nt][2] + bb.x, acc[mt][nt][3] + bb.y);
            *(float2*)&C[(size_t)row * N + col]       = c0;
            *(float2*)&C[(size_t)(row + 8) * N + col] = c1;
        }
    }
}

// ---------------- row L2 norm for tokens: g_Pin -> g_A (fp32) + g_Abf (bf16) ----------------
__global__ void k_rownorm() {
    int rw = blockIdx.x, t = threadIdx.x;
    float4 v = ((const float4*)(g_Pin + (size_t)rw * LDIM))[t];
    float s = blockSum(v.x*v.x + v.y*v.y + v.z*v.z + v.w*v.w, 128);
    float r = rsqrtf(s + 1e-12f);
    float4 o = make_float4(v.x*r, v.y*r, v.z*r, v.w*r);
    ((float4*)(g_A + (size_t)rw * LDIM))[t] = o;
    __nv_bfloat162* ob = (__nv_bfloat162*)(g_Abf + (size_t)rw * LDIM);
    ob[t * 2 + 0] = __floats2bfloat162_rn(o.x, o.y);
    ob[t * 2 + 1] = __floats2bfloat162_rn(o.z, o.w);
}

// codes: double normalization (matches reference), exact ||b||^2, fp32 + bf16 copies
__global__ void k_codenorm() {
    int rw = blockIdx.x, t = threadIdx.x;
    float4 v = ((const float4*)(g_Pcode + (size_t)rw * LDIM))[t];
    float s1 = blockSum(v.x*v.x + v.y*v.y + v.z*v.z + v.w*v.w, 128);
    float r1 = rsqrtf(s1 + 1e-12f);
    v = make_float4(v.x*r1, v.y*r1, v.z*r1, v.w*r1);
    float s2 = blockSum(v.x*v.x + v.y*v.y + v.z*v.z + v.w*v.w, 128);
    float r2 = rsqrtf(s2 + 1e-12f);
    v = make_float4(v.x*r2, v.y*r2, v.z*r2, v.w*r2);
    float s3 = blockSum(v.x*v.x + v.y*v.y + v.z*v.z + v.w*v.w, 128);
    ((float4*)(g_C + (size_t)rw * LDIM))[t] = v;
    __nv_bfloat162* ob = (__nv_bfloat162*)(g_Cbf + (size_t)rw * LDIM);
    ob[t * 2 + 0] = __floats2bfloat162_rn(v.x, v.y);
    ob[t * 2 + 1] = __floats2bfloat162_rn(v.z, v.w);
    if (t == 0) g_b2[rw] = s3;
}

// ---------------- bf16 tensor-core scorer ----------------
// Tile 128 tokens x 128 codes, K=512 in 8 chunks of 64. 8 warps: 4(m) x 2(n),
// warp tile 32x64 via mma.m16n8k16 (2 m-tiles x 8 n-tiles).
// Smem: 8x8 uint4-block XOR swizzle -> conflict-free LDS.32 fragment loads.
// Epilogue: s = b2[v] - 2*dot; store fp16 score matrix + per-row approx-min atomicMin.
__global__ __launch_bounds__(256) void k_score() {
    __shared__ __align__(16) __nv_bfloat16 As[128 * 64];
    __shared__ __align__(16) __nv_bfloat16 Cs[128 * 64];
    __shared__ unsigned long long red[128 * 2];

    const int tid = threadIdx.x;
    const int wid = tid >> 5, lane = tid & 31;
    const int warp_m = wid >> 1, warp_n = wid & 1;
    const int g = lane >> 2, q = lane & 3;
    const int bm0 = blockIdx.y * 128;   // token tile
    const int bv0 = blockIdx.x * 128;   // code tile

    float acc[2][8][4];
    #pragma unroll
    for (int mt = 0; mt < 2; mt++)
        #pragma unroll
        for (int nt = 0; nt < 8; nt++)
            #pragma unroll
            for (int i = 0; i < 4; i++) acc[mt][nt][i] = 0.f;

    const uint4* Ag = (const uint4*)(g_Abf + (size_t)bm0 * LDIM);
    const uint4* Cg = (const uint4*)(g_Cbf + (size_t)bv0 * LDIM);
    uint4* As4 = (uint4*)As;
    uint4* Cs4 = (uint4*)Cs;
    const unsigned int* As32 = (const unsigned int*)As;
    const unsigned int* Cs32 = (const unsigned int*)Cs;

    for (int kc = 0; kc < 8; kc++) {
        __syncthreads();   // previous chunk's compute done before overwrite
        #pragma unroll
        for (int i = 0; i < 4; i++) {
            int idx = tid + i * 256;            // 0..1023
            int row = idx >> 3, wq = idx & 7;   // 8 uint4 per 64-elem row
            As4[row * 8 + (wq ^ (row & 7))] = Ag[(size_t)row * 64 + kc * 8 + wq];
            Cs4[row * 8 + (wq ^ (row & 7))] = Cg[(size_t)row * 64 + kc * 8 + wq];
        }
        __syncthreads();
        #pragma unroll
        for (int ks = 0; ks < 4; ks++) {
            unsigned int af[2][4];
            #pragma unroll
            for (int mt = 0; mt < 2; mt++) {
                int r0 = warp_m * 32 + mt * 16 + g;
                int r1 = r0 + 8;
                af[mt][0] = As32[r0*32 + (((ks*2 + 0) ^ (r0 & 7)) << 2) + q];
                af[mt][1] = As32[r1*32 + (((ks*2 + 0) ^ (r1 & 7)) << 2) + q];
                af[mt][2] = As32[r0*32 + (((ks*2 + 1) ^ (r0 & 7)) << 2) + q];
                af[mt][3] = As32[r1*32 + (((ks*2 + 1) ^ (r1 & 7)) << 2) + q];
            }
            #pragma unroll
            for (int nt = 0; nt < 8; nt++) {
                int rc = warp_n * 64 + nt * 8 + g;
                unsigned int b0 = Cs32[rc*32 + (((ks*2 + 0) ^ (rc & 7)) << 2) + q];
                unsigned int b1 = Cs32[rc*32 + (((ks*2 + 1) ^ (rc & 7)) << 2) + q];
                mma16816(acc[0][nt], af[0], b0, b1);
                mma16816(acc[1][nt], af[1], b0, b1);
            }
        }
    }

    // epilogue: scores, fp16 store, per-row approx min
    unsigned long long km[2][2];
    km[0][0] = km[0][1] = km[1][0] = km[1][1] = 0xFFFFFFFFFFFFFFFFull;

    #pragma unroll
    for (int nt = 0; nt < 8; nt++) {
        int colG = bv0 + warp_n * 64 + nt * 8 + q * 2;
        float2 bb = *(const float2*)&g_b2[colG];
        #pragma unroll
        for (int mt = 0; mt < 2; mt++) {
            float s0 = bb.x - 2.f * acc[mt][nt][0];
            float s1 = bb.y - 2.f * acc[mt][nt][1];
            float s2 = bb.x - 2.f * acc[mt][nt][2];
            float s3 = bb.y - 2.f * acc[mt][nt][3];
            int r0 = bm0 + warp_m * 32 + mt * 16 + g;
            *(__half2*)&g_S[(size_t)r0 * VSZ + colG]       = __floats2half2_rn(s0, s1);
            *(__half2*)&g_S[(size_t)(r0 + 8) * VSZ + colG] = __floats2half2_rn(s2, s3);
            unsigned long long p0 =
                ((unsigned long long)fkey(s0) << 32) | (unsigned int)colG;
            unsigned long long p1 =
                ((unsigned long long)fkey(s1) << 32) | (unsigned int)(colG + 1);
            if (p1 < p0) p0 = p1;
            if (p0 < km[mt][0]) km[mt][0] = p0;
            unsigned long long p2 =
                ((unsigned long long)fkey(s2) << 32) | (unsigned int)colG;
            unsigned long long p3 =
                ((unsigned long long)fkey(s3) << 32) | (unsigned int)(colG + 1);
            if (p3 < p2) p2 = p3;
            if (p2 < km[mt][1]) km[mt][1] = p2;
        }
    }
    // reduce across the 4 lanes of each quad (same row)
    #pragma unroll
    for (int mt = 0; mt < 2; mt++)
        #pragma unroll
        for (int h = 0; h < 2; h++) {
            unsigned long long v = km[mt][h];
            #pragma unroll
            for (int off = 1; off < 4; off <<= 1) {
                unsigned long long o = __shfl_xor_sync(0xffffffffu, v, off);
                if (o < v) v = o;
            }
            km[mt][h] = v;
        }
    if (q == 0) {
        #pragma unroll
        for (int mt = 0; mt < 2; mt++)
            #pragma unroll
            for (int h = 0; h < 2; h++) {
                int r = warp_m * 32 + mt * 16 + h * 8 + g;
                red[r * 2 + warp_n] = km[mt][h];
            }
    }
    __syncthreads();
    if (tid < 128) {
        unsigned long long m = red[tid * 2];
        if (red[tid * 2 + 1] < m) m = red[tid * 2 + 1];
        atomicMin(&g_best[bm0 + tid], m);
    }
}

// ---------------- candidate filter + exact fp32 rescore (one block per token) ----------------
__global__ __launch_bounds__(256) void k_select() {
    const int n = blockIdx.x, tid = threadIdx.x;
    __shared__ int cnt;
    __shared__ int cand[256];
    __shared__ unsigned long long bestSh;
    if (tid == 0) { cnt = 0; bestSh = 0xFFFFFFFFFFFFFFFFull; }
    __syncthreads();

    const float thr = keyfloat((unsigned int)(g_best[n] >> 32)) + DELTA;
    const __half2* rowS = (const __half2*)(g_S + (size_t)n * VSZ);
    for (int v2 = tid; v2 < VSZ / 2; v2 += 256) {
        float2 f = __half22float2(rowS[v2]);
        if (f.x <= thr) { int p = atomicAdd(&cnt, 1); if (p < 256) cand[p] = v2 * 2; }
        if (f.y <= thr) { int p = atomicAdd(&cnt, 1); if (p < 256) cand[p] = v2 * 2 + 1; }
    }
    __syncthreads();
    int c = cnt;

    unsigned long long best = 0xFFFFFFFFFFFFFFFFull;
    if (c <= 256) {
        const float* ar = g_A + (size_t)n * LDIM;
        for (int i = 0; i < c; i++) {
            int v = cand[i];
            const float* cr = g_C + (size_t)v * LDIM;
            float part = ar[tid * 2] * cr[tid * 2] + ar[tid * 2 + 1] * cr[tid * 2 + 1];
            float s = blockSum(part, 256);
            float score = g_b2[v] - 2.f * s;
            unsigned long long p =
                ((unsigned long long)fkey(score) << 32) | (unsigned int)v;
            if (p < best) best = p;
        }
    } else {
        // safety fallback (statistically never): full exact scan for this token
        const float* ar = g_A + (size_t)n * LDIM;
        unsigned long long loc = 0xFFFFFFFFFFFFFFFFull;
        for (int v = tid; v < VSZ; v += 256) {
            const float* cr = g_C + (size_t)v * LDIM;
            float s = 0.f;
            for (int d = 0; d < LDIM; d++) s += ar[d] * cr[d];
            float score = g_b2[v] - 2.f * s;
            unsigned long long p =
                ((unsigned long long)fkey(score) << 32) | (unsigned int)v;
            if (p < loc) loc = p;
        }
        atomicMin(&bestSh, loc);
        __syncthreads();
        best = bestSh;
    }

    if (tid == 0) {
        int id = (int)(best & 0xFFFFFFFFull);
        g_idx[n] = id;
        atomicAdd(&g_count[id], 1);
    }
}

// ---------------- quantized_st output + commit MSE ----------------
__global__ void k_quant(const float* __restrict__ x, const float* __restrict__ cb,
                        float* __restrict__ out)
{
    int n = blockIdx.x, t = threadIdx.x;
    int id = g_idx[n];
    float4 xv = ((const float4*)(x  + (size_t)n  * DDIM))[t];
    float4 qv = ((const float4*)(cb + (size_t)id * DDIM))[t];
    float4 d = make_float4(qv.x - xv.x, qv.y - xv.y, qv.z - xv.z, qv.w - xv.w);
    ((float4*)(out + (size_t)n * DDIM))[t] =
        make_float4(xv.x + d.x, xv.y + d.y, xv.z + d.z, xv.w + d.w);
    float loc = d.x*d.x + d.y*d.y + d.z*d.z + d.w*d.w;
    float s = blockSum(loc, 256);
    if (t == 0) atomicAdd(&g_sum1, (double)s);
}

// ---------------- latent-space MSE ----------------
__global__ void k_l2loss() {
    int n = blockIdx.x, t = threadIdx.x;
    int id = g_idx[n];
    float4 a = ((const float4*)(g_Pin   + (size_t)n  * LDIM))[t];
    float4 b = ((const float4*)(g_Pcode + (size_t)id * LDIM))[t];
    float4 d = make_float4(b.x - a.x, b.y - a.y, b.z - a.z, b.w - a.w);
    float loc = d.x*d.x + d.y*d.y + d.z*d.z + d.w*d.w;
    float s = blockSum(loc, 128);
    if (t == 0) atomicAdd(&g_sum2, (double)s);
}

// ---------------- final scalars: loss, perplexity, usage ----------------
__global__ void k_final(float* __restrict__ outScal) {
    __shared__ double shd[256];
    __shared__ int    shi[256];
    int t = threadIdx.x;
    double lp = 0.0;
    int used = 0;
    for (int v = t; v < VSZ; v += 256) {
        int c = g_count[v];
        if (c > 0) used++;
        float p = (float)c * (1.0f / 8192.0f);
        lp += (double)(-(p * logf(p + 1e-10f)));
    }
    shd[t] = lp; shi[t] = used;
    __syncthreads();
    for (int o = 128; o; o >>= 1) {
        if (t < o) { shd[t] += shd[t + o]; shi[t] += shi[t + o]; }
        __syncthreads();
    }
    if (t == 0) {
        float lpf = (float)shd[0];
        float m1 = (float)(g_sum1 / (double)((size_t)NTOK * DDIM));
        float m2 = (float)(g_sum2 / (double)((size_t)NTOK * LDIM));
        float loss = (0.25f * m1 + m1) + (0.25f * m2 + m2) + 0.1f * lpf;
        outScal[0] = loss;
        outScal[1] = expf(lpf);
        outScal[2] = (float)shi[0] / (float)VSZ;
    }
}

// ---------------- launch ----------------
extern "C" void kernel_launch(void* const* d_in, const int* in_sizes, int n_in,
                              void* d_out, int out_size)
{
    (void)in_sizes; (void)n_in;
    const float* x      = (const float*)d_in[0];
    const float* cb     = (const float*)d_in[1];
    const float* W_in   = (const float*)d_in[2];
    const float* b_in   = (const float*)d_in[3];
    const float* W_code = (const float*)d_in[4];
    const float* b_code = (const float*)d_in[5];
    float* out = (float*)d_out;

    // Host-resolved device-symbol addresses for kernels taking them as args.
    void *pPin, *pPcode;
    cudaGetSymbolAddress(&pPin,   g_Pin);
    cudaGetSymbolAddress(&pPcode, g_Pcode);

    k_init<<<(VSZ + 255) / 256, 256>>>();

    // latent_input = l2norm(x @ W_in + b_in); fp32-faithful tf32 3-pass GEMM
    k_gemm_tf32<<<dim3(LDIM / 128, NTOK / 128), 256>>>(
        x, W_in, b_in, (float*)pPin, NTOK, LDIM, DDIM);
    k_rownorm<<<NTOK, 128>>>();

    // latent_code (double-normalized) + exact ||b||^2
    k_gemm_tf32<<<dim3(LDIM / 128, VSZ / 128), 256>>>(
        cb, W_code, b_code, (float*)pPcode, VSZ, LDIM, DDIM);
    k_codenorm<<<VSZ, 128>>>();

    // bf16 tensor-core scoring: fp16 score matrix + approx per-token min
    k_score<<<dim3(VSZ / 128, NTOK / 128), 256>>>();

    // epsilon-filter + exact fp32 rescore -> final indices + histogram
    k_select<<<NTOK, 256>>>();

    k_quant<<<NTOK, 256>>>(x, cb, out);
    k_l2loss<<<NTOK, 128>>>();
    k_final<<<1, 256>>>(out + (out_size - 3));
}